// round 8
// baseline (speedup 1.0000x reference)
#include <cuda_runtime.h>
#include <cuda_bf16.h>
#include <cstdint>
#include <math.h>

// Problem dims (fixed)
#define BATCH  2
#define SEQ    2048
#define NH     16
#define DHD    128
#define DMODEL 2048
#define MROWS  (BATCH * SEQ)   // 4096
#define ATT_SCALE 0.08838834764831845f

// ---- arch-feature gate: tcgen05 only exists in the sm_103a/'a'/'f' passes ----
#if defined(__CUDA_ARCH__)
#  if defined(__CUDA_ARCH_FEAT_SM103_ALL) || defined(__CUDA_ARCH_FEAT_SM100_ALL)
#    define HAS_TCGEN05 1
#  elif defined(__CUDA_ARCH_SPECIFIC__) && (__CUDA_ARCH_SPECIFIC__ >= 1000)
#    define HAS_TCGEN05 1
#  elif defined(__CUDA_ARCH_FAMILY_SPECIFIC__) && (__CUDA_ARCH_FAMILY_SPECIFIC__ >= 1000)
#    define HAS_TCGEN05 1
#  else
#    define HAS_TCGEN05 0
#  endif
#else
#  define HAS_TCGEN05 0
#endif

typedef __nv_bfloat16 bf16;

// ===================== generic helpers ======================================
__device__ __forceinline__ uint32_t smem_u32(const void* p) {
    uint32_t a;
    asm("{ .reg .u64 t; cvta.to.shared.u64 t, %1; cvt.u32.u64 %0, t; }"
        : "=r"(a) : "l"(p));
    return a;
}

__device__ __forceinline__ uint32_t elect_one_pred() {
    uint32_t pred;
    asm volatile(
        "{\n\t.reg .pred p;\n\telect.sync _|p, 0xFFFFFFFF;\n\tselp.b32 %0, 1, 0, p;\n\t}"
        : "=r"(pred));
    return pred;
}

#define MBARRIER_INIT(addr, count) \
    asm volatile("mbarrier.init.shared.b64 [%0], %1;" :: "r"((uint32_t)(addr)), "r"((uint32_t)(count)) : "memory")

#define MBARRIER_WAIT_PARITY(mbar_smem_addr, phase_parity) do { \
    uint32_t _mbar = (uint32_t)(mbar_smem_addr); \
    uint32_t _parity = (uint32_t)(phase_parity); \
    uint32_t _done; \
    asm volatile( \
        "{\n\t.reg .pred p;\n\t" \
        "mbarrier.try_wait.parity.acquire.cta.shared::cta.b64 p, [%1], %2;\n\t" \
        "selp.b32 %0, 1, 0, p;\n\t}" \
        : "=r"(_done) : "r"(_mbar), "r"(_parity) : "memory"); \
    if (!_done) { \
        asm volatile( \
            "{\n\t.reg .pred P1;\n\t" \
            "WAIT_LOOP_%=:\n\t" \
            "mbarrier.try_wait.parity.acquire.cta.shared::cta.b64 P1, [%0], %1, 0x989680;\n\t" \
            "@P1 bra.uni WAIT_DONE_%=;\n\t" \
            "bra.uni WAIT_LOOP_%=;\n\t" \
            "WAIT_DONE_%=:\n\t}" \
            :: "r"(_mbar), "r"(_parity) : "memory"); \
    } \
} while(0)

__device__ __forceinline__ uint32_t sw128(uint32_t o) { return o ^ ((o >> 3) & 0x70); }

__device__ __forceinline__ void split2u32(float a, float b, uint32_t& hp, uint32_t& lp) {
    __nv_bfloat16 ha = __float2bfloat16(a), hb = __float2bfloat16(b);
    float ra = a - __bfloat162float(ha);
    float rb = b - __bfloat162float(hb);
    __nv_bfloat16 la = __float2bfloat16(ra), lb = __float2bfloat16(rb);
    hp = ((uint32_t)__bfloat16_as_ushort(hb) << 16) | __bfloat16_as_ushort(ha);
    lp = ((uint32_t)__bfloat16_as_ushort(lb) << 16) | __bfloat16_as_ushort(la);
}

#if HAS_TCGEN05
// ===================== tcgen05 PTX (guarded) ================================
#define TCGEN05_ALLOC(smem_result_addr, nCols) \
    asm volatile("tcgen05.alloc.cta_group::1.sync.aligned.shared::cta.b32 [%0], %1;" \
        :: "r"((uint32_t)(smem_result_addr)), "r"((uint32_t)(nCols)) : "memory")
#define TCGEN05_DEALLOC(tmem_addr, nCols) \
    asm volatile("tcgen05.dealloc.cta_group::1.sync.aligned.b32 %0, %1;" \
        :: "r"(tmem_addr), "r"((uint32_t)(nCols)))
#define TCGEN05_RELINQUISH() \
    asm volatile("tcgen05.relinquish_alloc_permit.cta_group::1.sync.aligned;")
#define TCGEN05_COMMIT(mbar_smem_addr) \
    asm volatile("tcgen05.commit.cta_group::1.mbarrier::arrive::one.shared::cluster.b64 [%0];" \
        :: "r"((uint32_t)(mbar_smem_addr)) : "memory")
#define TCGEN05_FENCE_AFTER() \
    asm volatile("tcgen05.fence::after_thread_sync;" ::: "memory")
#define TCGEN05_FENCE_BEFORE() \
    asm volatile("tcgen05.fence::before_thread_sync;" ::: "memory")
#define TCGEN05_WAIT_LD() \
    asm volatile("tcgen05.wait::ld.sync.aligned;" ::: "memory")
#define FENCE_PROXY_ASYNC_SHARED_CTA() \
    asm volatile("fence.proxy.async.shared::cta;" ::: "memory")

#define TCGEN05_LD_32X32B_X32(r, tmem_addr) \
    asm volatile( \
        "tcgen05.ld.sync.aligned.32x32b.x32.b32 " \
        "{%0, %1, %2, %3, %4, %5, %6, %7, " \
        " %8, %9, %10, %11, %12, %13, %14, %15, " \
        " %16, %17, %18, %19, %20, %21, %22, %23, " \
        " %24, %25, %26, %27, %28, %29, %30, %31}, [%32];" \
        : "=r"((r)[0]),  "=r"((r)[1]),  "=r"((r)[2]),  "=r"((r)[3]), \
          "=r"((r)[4]),  "=r"((r)[5]),  "=r"((r)[6]),  "=r"((r)[7]), \
          "=r"((r)[8]),  "=r"((r)[9]),  "=r"((r)[10]), "=r"((r)[11]), \
          "=r"((r)[12]), "=r"((r)[13]), "=r"((r)[14]), "=r"((r)[15]), \
          "=r"((r)[16]), "=r"((r)[17]), "=r"((r)[18]), "=r"((r)[19]), \
          "=r"((r)[20]), "=r"((r)[21]), "=r"((r)[22]), "=r"((r)[23]), \
          "=r"((r)[24]), "=r"((r)[25]), "=r"((r)[26]), "=r"((r)[27]), \
          "=r"((r)[28]), "=r"((r)[29]), "=r"((r)[30]), "=r"((r)[31]) \
        : "r"(tmem_addr))

static constexpr uint64_t SMEM_DESC_BASE_SW128 =
    (uint64_t(2)  << 61) | (uint64_t(1) << 46) | (uint64_t(64) << 32) | (uint64_t(1) << 16);
#define MAKE_SMEM_DESC(base_addr) \
    (SMEM_DESC_BASE_SW128 | ((uint64_t)((base_addr) >> 4) & 0x3FFF))

__device__ __forceinline__ void mma_f16_ss(uint32_t d, uint64_t da, uint64_t db,
                                           uint32_t idesc, bool en) {
    uint32_t e = en ? 1u : 0u;
    asm volatile(
        "{\n\t.reg .pred p;\n\tsetp.ne.u32 p, %5, 0;\n\t"
        "tcgen05.mma.cta_group::1.kind::f16 [%0], %1, %2, %3, {%4, %4, %4, %4}, p;\n\t}"
        :: "r"(d), "l"(da), "l"(db), "r"(idesc), "r"(0u), "r"(e) : "memory");
}
#endif  // HAS_TCGEN05

// ===================== scratch ==============================================
__device__ float g_Qr[(size_t)MROWS * DMODEL];
__device__ float g_Kr[(size_t)MROWS * DMODEL];
__device__ float g_Vr[(size_t)MROWS * DMODEL];
__device__ float g_cos[SEQ * (DHD / 2)];
__device__ float g_sin[SEQ * (DHD / 2)];

__device__ bf16 g_xh[(size_t)MROWS * DMODEL];
__device__ bf16 g_xl[(size_t)MROWS * DMODEL];
__device__ bf16 g_Wqh[(size_t)DMODEL * DMODEL];
__device__ bf16 g_Wql[(size_t)DMODEL * DMODEL];
__device__ bf16 g_Wkh[(size_t)DMODEL * DMODEL];
__device__ bf16 g_Wkl[(size_t)DMODEL * DMODEL];
__device__ bf16 g_Wvh[(size_t)DMODEL * DMODEL];
__device__ bf16 g_Wvl[(size_t)DMODEL * DMODEL];
__device__ bf16 g_Woh[(size_t)DMODEL * DMODEL];
__device__ bf16 g_Wol[(size_t)DMODEL * DMODEL];
__device__ bf16 g_Qsh[(size_t)MROWS * DMODEL];
__device__ bf16 g_Qsl[(size_t)MROWS * DMODEL];
__device__ bf16 g_Ksh[(size_t)MROWS * DMODEL];
__device__ bf16 g_Ksl[(size_t)MROWS * DMODEL];
// V transposed per (b,h): [b][h][d=128][s=2048]
__device__ bf16 g_Vth[(size_t)MROWS * DMODEL];
__device__ bf16 g_Vtl[(size_t)MROWS * DMODEL];
__device__ bf16 g_Aoh[(size_t)MROWS * DMODEL];
__device__ bf16 g_Aol[(size_t)MROWS * DMODEL];

// ===================== RoPE table ===========================================
__global__ void rope_table_kernel() {
    int idx = blockIdx.x * blockDim.x + threadIdx.x;
    if (idx >= SEQ * (DHD / 2)) return;
    int s = idx / (DHD / 2);
    int i = idx % (DHD / 2);
    double inv = pow(10000.0, -(double)(2 * i) / (double)DHD);
    double f = (double)s * inv;
    g_cos[idx] = (float)cos(f);
    g_sin[idx] = (float)sin(f);
}

// ===================== split converters =====================================
__global__ void convert_split_kernel(const float* __restrict__ in,
                                     bf16* __restrict__ hi, bf16* __restrict__ lo,
                                     int n)
{
    int i = (blockIdx.x * blockDim.x + threadIdx.x) * 4;
    if (i >= n) return;
    float4 v = *(const float4*)(in + i);
    uint32_t h0, l0, h1, l1;
    split2u32(v.x, v.y, h0, l0);
    split2u32(v.z, v.w, h1, l1);
    *(uint2*)(hi + i) = make_uint2(h0, h1);
    *(uint2*)(lo + i) = make_uint2(l0, l1);
}

__device__ __forceinline__ void split_store(bf16* hi, bf16* lo, size_t idx, float v) {
    __nv_bfloat16 h = __float2bfloat16(v);
    float r = v - __bfloat162float(h);
    hi[idx] = h;
    lo[idx] = __float2bfloat16(r);
}

// RoPE on Q (softmax scale folded) and K, split to bf16.
__global__ void rope_convert_kernel() {
    int bs = blockIdx.x;
    int s = bs % SEQ;
    int t = threadIdx.x;
    int h = t >> 6;
    int i = t & 63;
    size_t base = (size_t)bs * DMODEL + (size_t)h * DHD;
    float c  = g_cos[s * 64 + i];
    float sn = g_sin[s * 64 + i];

    float q1 = g_Qr[base + i];
    float q2 = g_Qr[base + i + 64];
    float qa = (q1 * c - q2 * sn) * ATT_SCALE;
    float qb = (q2 * c + q1 * sn) * ATT_SCALE;
    split_store(g_Qsh, g_Qsl, base + i, qa);
    split_store(g_Qsh, g_Qsl, base + i + 64, qb);

    float k1 = g_Kr[base + i];
    float k2 = g_Kr[base + i + 64];
    float ka = k1 * c - k2 * sn;
    float kb = k2 * c + k1 * sn;
    split_store(g_Ksh, g_Ksl, base + i, ka);
    split_store(g_Ksh, g_Ksl, base + i + 64, kb);
}

// ===================== V transpose+split: [bs][h*128+d] -> [b][h][d][s] =====
#define VT_SMEM ((128 * 130) * 4)
__global__ void vtrans_kernel() {
    extern __shared__ float vs[];   // [128 s][130 pad d]
    const int tid = threadIdx.x;
    const int s0 = blockIdx.x * 128;
    const int h  = blockIdx.y;
    const int b  = blockIdx.z;

#pragma unroll
    for (int i = 0; i < 16; i++) {
        int f4 = tid + i * 256;
        int s = f4 >> 5;
        int c4 = (f4 & 31) * 4;
        float4 v = *(const float4*)(g_Vr + (size_t)(b * SEQ + s0 + s) * DMODEL
                                         + h * DHD + c4);
        vs[s * 130 + c4 + 0] = v.x;
        vs[s * 130 + c4 + 1] = v.y;
        vs[s * 130 + c4 + 2] = v.z;
        vs[s * 130 + c4 + 3] = v.w;
    }
    __syncthreads();

    const int d = tid >> 1;
    const int sh = tid & 1;
    size_t gb = ((size_t)(b * NH + h) * DHD + d) * SEQ + s0 + sh * 64;
#pragma unroll
    for (int g = 0; g < 8; g++) {
        uint32_t hh[4], ll[4];
#pragma unroll
        for (int p = 0; p < 4; p++) {
            float a = vs[(sh * 64 + g * 8 + 2 * p) * 130 + d];
            float bb = vs[(sh * 64 + g * 8 + 2 * p + 1) * 130 + d];
            split2u32(a, bb, hh[p], ll[p]);
        }
        *(uint4*)(g_Vth + gb + g * 8) = make_uint4(hh[0], hh[1], hh[2], hh[3]);
        *(uint4*)(g_Vtl + gb + g * 8) = make_uint4(ll[0], ll[1], ll[2], ll[3]);
    }
}

// ===================== GEMM 128x256 tiles (bf16 split) ======================
#define TCBM 128
#define TCBN 256
#define TCBK 64
#define NCHUNK (DMODEL / TCBK)        // 32
#define STAGE_BYTES 98304             // A hi/lo 16KB each + B hi/lo 32KB each
#define GEMM_DSMEM (2 * STAGE_BYTES + 1024)

#define GEMM_IDESC ((1u<<4) | (1u<<7) | (1u<<10) | (32u<<17) | (8u<<24))  // N=256,M=128

template <bool BIAS>
__global__ void __launch_bounds__(256) gemm_kernel(
    const bf16* __restrict__ Ahi, const bf16* __restrict__ Alo,
    const bf16* __restrict__ Whi, const bf16* __restrict__ Wlo,
    const float* __restrict__ bias, float* __restrict__ C)
{
#if HAS_TCGEN05
    extern __shared__ char dsm[];
    __shared__ uint32_t s_tmem[1];
    __shared__ __align__(8) uint64_t s_mbar[2];

    uint32_t dyn = smem_u32(dsm);
    uint32_t base = (dyn + 1023) & ~1023u;
    char* bufc = dsm + (base - dyn);

    const int tid = threadIdx.x;
    const int wid = tid >> 5, lid = tid & 31;
    const int m0 = blockIdx.y * TCBM;
    const int n0 = blockIdx.x * TCBN;

    if (wid == 0) TCGEN05_ALLOC(smem_u32(s_tmem), 256);
    if (tid == 0) {
        MBARRIER_INIT(smem_u32(&s_mbar[0]), 1);
        MBARRIER_INIT(smem_u32(&s_mbar[1]), 1);
    }
    __syncthreads();
    const uint32_t tmem = s_tmem[0];
    const uint32_t mbar0 = smem_u32(&s_mbar[0]);
    const uint32_t mbar1 = smem_u32(&s_mbar[1]);

    const int ra = tid >> 1;        // A row
    const int half = tid & 1;       // A d-half

    for (int c = 0; c < NCHUNK; c++) {
        const int b = c & 1;
        if (c >= 2) {
            MBARRIER_WAIT_PARITY(b ? mbar1 : mbar0, ((c >> 1) - 1) & 1);
        }
        char* sAh = bufc + b * STAGE_BYTES;
        char* sAl = sAh + 16384;
        char* sBh = sAh + 32768;
        char* sBl = sAh + 65536;
        const int k0 = c * TCBK;
        // A: 128 rows x 64 k (2 threads/row)
        {
            const bf16* pAh = Ahi + (size_t)(m0 + ra) * DMODEL + k0 + half * 32;
            const bf16* pAl = Alo + (size_t)(m0 + ra) * DMODEL + k0 + half * 32;
#pragma unroll
            for (int j = 0; j < 4; j++) {
                uint32_t off = sw128((uint32_t)(ra * 128 + half * 64 + j * 16));
                *(uint4*)(sAh + off) = *(const uint4*)(pAh + j * 8);
                *(uint4*)(sAl + off) = *(const uint4*)(pAl + j * 8);
            }
        }
        // B: 256 rows x 64 k (1 thread/row)
        {
            const bf16* pWh = Whi + (size_t)(n0 + tid) * DMODEL + k0;
            const bf16* pWl = Wlo + (size_t)(n0 + tid) * DMODEL + k0;
#pragma unroll
            for (int j = 0; j < 8; j++) {
                uint32_t off = sw128((uint32_t)(tid * 128 + j * 16));
                *(uint4*)(sBh + off) = *(const uint4*)(pWh + j * 8);
                *(uint4*)(sBl + off) = *(const uint4*)(pWl + j * 8);
            }
        }
        FENCE_PROXY_ASYNC_SHARED_CTA();
        __syncthreads();

        if (wid == 0 && elect_one_pred()) {
            uint64_t dAh = MAKE_SMEM_DESC(smem_u32(sAh));
            uint64_t dAl = MAKE_SMEM_DESC(smem_u32(sAl));
            uint64_t dBh = MAKE_SMEM_DESC(smem_u32(sBh));
            uint64_t dBl = MAKE_SMEM_DESC(smem_u32(sBl));
            uint64_t pa[3] = {dAh, dAh, dAl};
            uint64_t pb[3] = {dBh, dBl, dBh};
#pragma unroll
            for (int pass = 0; pass < 3; pass++) {
#pragma unroll
                for (int k = 0; k < 4; k++) {
                    bool en = !(c == 0 && pass == 0 && k == 0);
                    mma_f16_ss(tmem, pa[pass] + k * 2, pb[pass] + k * 2, GEMM_IDESC, en);
                }
            }
            TCGEN05_COMMIT(b ? mbar1 : mbar0);
        }
    }

    const uint32_t fin_par = ((NCHUNK >> 1) - 1) & 1;
    MBARRIER_WAIT_PARITY(mbar0, fin_par);
    MBARRIER_WAIT_PARITY(mbar1, fin_par);
    TCGEN05_FENCE_AFTER();

    if (wid < 4) {
        const int mrow = m0 + wid * 32 + lid;
#pragma unroll
        for (int part = 0; part < 8; part++) {
            uint32_t d[32];
            TCGEN05_LD_32X32B_X32(d, tmem + part * 32);
            TCGEN05_WAIT_LD();
            float* crow = C + (size_t)mrow * DMODEL + n0 + part * 32;
#pragma unroll
            for (int q = 0; q < 8; q++) {
                float4 v;
                v.x = __uint_as_float(d[4*q + 0]);
                v.y = __uint_as_float(d[4*q + 1]);
                v.z = __uint_as_float(d[4*q + 2]);
                v.w = __uint_as_float(d[4*q + 3]);
                if (BIAS) {
                    const float* bp = bias + n0 + part * 32 + 4 * q;
                    v.x += bp[0]; v.y += bp[1]; v.z += bp[2]; v.w += bp[3];
                }
                *(float4*)(crow + 4 * q) = v;
            }
        }
        TCGEN05_FENCE_BEFORE();
    }
    __syncthreads();
    if (wid == 0) {
        TCGEN05_RELINQUISH();
        TCGEN05_DEALLOC(tmem, 256);
    }
#else
    // ---------------- SIMT fallback (dead on GB300; correctness backstop) ---
    const int tid = threadIdx.x;
    const int m0 = blockIdx.y * TCBM;
    const int n0 = blockIdx.x * TCBN;
    const int tx = tid % 16;
    const int ty = tid / 16;
    for (int jj = 0; jj < 2; jj++) {
        float acc[8][8];
        for (int i = 0; i < 8; i++)
            for (int j = 0; j < 8; j++) acc[i][j] = 0.0f;
        for (int k = 0; k < DMODEL; k++) {
            float a[8], bb[8];
            for (int i = 0; i < 8; i++) {
                size_t ai = (size_t)(m0 + ty * 8 + i) * DMODEL + k;
                a[i] = __bfloat162float(Ahi[ai]) + __bfloat162float(Alo[ai]);
            }
            for (int j = 0; j < 8; j++) {
                size_t bi = (size_t)(n0 + jj * 128 + tx * 8 + j) * DMODEL + k;
                bb[j] = __bfloat162float(Whi[bi]) + __bfloat162float(Wlo[bi]);
            }
            for (int i = 0; i < 8; i++)
                for (int j = 0; j < 8; j++) acc[i][j] += a[i] * bb[j];
        }
        for (int i = 0; i < 8; i++)
            for (int j = 0; j < 8; j++) {
                float v = acc[i][j];
                if (BIAS) v += bias[n0 + jj * 128 + tx * 8 + j];
                C[(size_t)(m0 + ty * 8 + i) * DMODEL + n0 + jj * 128 + tx * 8 + j] = v;
            }
    }
#endif
}

// ===================== tcgen05 flash attention (pipelined) ==================
// CTA: 128 queries x (b,h). 32 K-tiles of 64. TMEM: S0@0, S1@64, O@128.
// Double-buffered K and V smem; PV(t) + S(t+1) issued back-to-back.
#define ATQ 128
#define ATK 64
#define NT (SEQ / ATK)           // 32
#define AT_DSMEM (229376 + 1024)

#define IDESC_S ((1u<<4) | (1u<<7) | (1u<<10) | (8u<<17)  | (8u<<24))   // N=64
#define IDESC_O ((1u<<4) | (1u<<7) | (1u<<10) | (16u<<17) | (8u<<24))   // N=128

__global__ void __launch_bounds__(256, 1) attn_tc_kernel() {
#if HAS_TCGEN05
    extern __shared__ char smem_dyn[];
    __shared__ uint32_t s_tmem[1];
    __shared__ __align__(8) uint64_t s_mbar[3];
    __shared__ float l_sh[ATQ];

    uint32_t dyn = smem_u32(smem_dyn);
    uint32_t ab = (dyn + 1023) & ~1023u;
    char* B = smem_dyn + (ab - dyn);
    // layout (offsets in KB):
    char* Q0h = B;                  // 0   (16KB) d 0-63  hi
    char* Q1h = B + 16384;          // 16  (16KB) d 64-127 hi
    char* Q0l = B + 32768;          // 32
    char* Q1l = B + 49152;          // 48
    char* Kst[2];  Kst[0] = B + 65536;  Kst[1] = B + 98304;   // 32KB each: K0h,K1h,K0l,K1l @8KB
    char* Vst[2];  Vst[0] = B + 131072; Vst[1] = B + 163840;  // 32KB each: Vh(16KB),Vl(16KB)
    char* Phi = B + 196608;         // 192 (16KB)
    char* Plo = B + 212992;         // 208 (16KB)

    const int tid = threadIdx.x;
    const int wid = tid >> 5, lid = tid & 31;
    const int q0 = blockIdx.x * ATQ;
    const int h  = blockIdx.y;
    const int b  = blockIdx.z;

    if (wid == 0) TCGEN05_ALLOC(smem_u32(s_tmem), 256);
    if (tid == 0) {
        MBARRIER_INIT(smem_u32(&s_mbar[0]), 1);
        MBARRIER_INIT(smem_u32(&s_mbar[1]), 1);
        MBARRIER_INIT(smem_u32(&s_mbar[2]), 1);
    }
    for (int i = tid; i < ATQ; i += 256) l_sh[i] = 0.0f;
    __syncthreads();
    const uint32_t tmem = s_tmem[0];
    const uint32_t tmO = tmem + 128;
    const uint32_t mbS[2] = { smem_u32(&s_mbar[0]), smem_u32(&s_mbar[1]) };
    const uint32_t mbPV = smem_u32(&s_mbar[2]);

    // ---- persistent Q tile ----
    {
        const int r = tid >> 1, half = tid & 1;
        const bf16* gh = g_Qsh + (size_t)(b * SEQ + q0 + r) * DMODEL + h * DHD + half * 64;
        const bf16* gl = g_Qsl + (size_t)(b * SEQ + q0 + r) * DMODEL + h * DHD + half * 64;
        char* dh = half ? Q1h : Q0h;
        char* dl = half ? Q1l : Q0l;
#pragma unroll
        for (int j = 0; j < 8; j++) {
            uint32_t off = sw128((uint32_t)(r * 128 + j * 16));
            *(uint4*)(dh + off) = *(const uint4*)(gh + j * 8);
            *(uint4*)(dl + off) = *(const uint4*)(gl + j * 8);
        }
    }

    const uint64_t dQ[2][2] = {
        { MAKE_SMEM_DESC(smem_u32(Q0h)), MAKE_SMEM_DESC(smem_u32(Q1h)) },
        { MAKE_SMEM_DESC(smem_u32(Q0l)), MAKE_SMEM_DESC(smem_u32(Q1l)) } };
    const uint64_t dPh = MAKE_SMEM_DESC(smem_u32(Phi));
    const uint64_t dPl = MAKE_SMEM_DESC(smem_u32(Plo));

    // K tile loader: stage st, tile index tt
    auto load_k = [&](int st, int tt) {
        const int k0 = tt * ATK;
        const int r = tid >> 2, seg = tid & 3;
        const int d0 = seg * 32;
        char* dh = Kst[st] + (seg >> 1) * 8192;            // K0h or K1h
        char* dl = dh + 16384;                             // matching lo
        const bf16* gh = g_Ksh + (size_t)(b * SEQ + k0 + r) * DMODEL + h * DHD + d0;
        const bf16* gl = g_Ksl + (size_t)(b * SEQ + k0 + r) * DMODEL + h * DHD + d0;
#pragma unroll
        for (int j = 0; j < 4; j++) {
            uint32_t off = sw128((uint32_t)(r * 128 + (d0 & 63) * 2 + j * 16));
            *(uint4*)(dh + off) = *(const uint4*)(gh + j * 8);
            *(uint4*)(dl + off) = *(const uint4*)(gl + j * 8);
        }
    };
    // V tile loader (pre-transposed gmem): rows = d (128), cols = k (64)
    auto load_v = [&](int st, int tt) {
        const int k0 = tt * ATK;
        const int d = tid >> 1, half = tid & 1;
        size_t gb = ((size_t)(b * NH + h) * DHD + d) * SEQ + k0 + half * 32;
        char* vh = Vst[st];
        char* vl = Vst[st] + 16384;
#pragma unroll
        for (int j = 0; j < 4; j++) {
            uint32_t off = sw128((uint32_t)(d * 128 + half * 64 + j * 16));
            *(uint4*)(vh + off) = *(const uint4*)(g_Vth + gb + j * 8);
            *(uint4*)(vl + off) = *(const uint4*)(g_Vtl + gb + j * 8);
        }
    };

    auto issue_S = [&](int tt) {   // elected thread only
        const uint32_t dst = tmem + (tt & 1) * 64;
        uint64_t dKh = MAKE_SMEM_DESC(smem_u32(Kst[tt & 1]));          // K0h
        uint64_t dK1h = MAKE_SMEM_DESC(smem_u32(Kst[tt & 1] + 8192));  // K1h
        uint64_t dKl = MAKE_SMEM_DESC(smem_u32(Kst[tt & 1] + 16384));
        uint64_t dK1l = MAKE_SMEM_DESC(smem_u32(Kst[tt & 1] + 24576));
        uint64_t kk[2][2] = { {dKh, dK1h}, {dKl, dK1l} };
        const int pa[3] = {0, 0, 1};
        const int pb[3] = {0, 1, 0};
#pragma unroll
        for (int pass = 0; pass < 3; pass++) {
#pragma unroll
            for (int cd = 0; cd < 8; cd++) {
                uint64_t da = dQ[pa[pass]][cd >> 2] + (cd & 3) * 2;
                uint64_t db = kk[pb[pass]][cd >> 2] + (cd & 3) * 2;
                mma_f16_ss(dst, da, db, IDESC_S, !(pass == 0 && cd == 0));
            }
        }
        TCGEN05_COMMIT(mbS[tt & 1]);
    };

    // ---- prologue: K0,V0; issue S0 ----
    load_k(0, 0);
    load_v(0, 0);
    FENCE_PROXY_ASYNC_SHARED_CTA();
    __syncthreads();
    if (wid == 0 && elect_one_pred()) issue_S(0);

    const int qrow = (wid & 3) * 32 + lid;
    const int c0 = (wid >> 2) * 32;

    for (int t = 0; t < NT; t++) {
        // free P, V[(t-1)&1], then prefetch tile t+1
        if (t >= 1) MBARRIER_WAIT_PARITY(mbPV, (t - 1) & 1);
        if (t + 1 < NT) {
            load_k((t + 1) & 1, t + 1);
            load_v((t + 1) & 1, t + 1);
        }
        // S t ready?
        MBARRIER_WAIT_PARITY(mbS[t & 1], (t >> 1) & 1);
        TCGEN05_FENCE_AFTER();
        // exp + split-store P
        {
            uint32_t sr[32];
            TCGEN05_LD_32X32B_X32(sr, tmem + (t & 1) * 64 + c0);
            TCGEN05_WAIT_LD();
            TCGEN05_FENCE_BEFORE();
            float rs = 0.0f;
            uint32_t hp[16], lp[16];
#pragma unroll
            for (int i = 0; i < 16; i++) {
                float p0 = __expf(__uint_as_float(sr[2 * i]));
                float p1 = __expf(__uint_as_float(sr[2 * i + 1]));
                rs += p0 + p1;
                split2u32(p0, p1, hp[i], lp[i]);
            }
#pragma unroll
            for (int i = 0; i < 16; i++) {
                uint32_t off = sw128((uint32_t)(qrow * 128 + (c0 + 2 * i) * 2));
                *(uint32_t*)(Phi + off) = hp[i];
                *(uint32_t*)(Plo + off) = lp[i];
            }
            atomicAdd(&l_sh[qrow], rs);
        }
        FENCE_PROXY_ASYNC_SHARED_CTA();
        __syncthreads();
        // issue PV t then S t+1 (back-to-back tensor work)
        if (wid == 0 && elect_one_pred()) {
            uint64_t dVh = MAKE_SMEM_DESC(smem_u32(Vst[t & 1]));
            uint64_t dVl = MAKE_SMEM_DESC(smem_u32(Vst[t & 1] + 16384));
#pragma unroll
            for (int pass = 0; pass < 3; pass++) {
                uint64_t da = (pass < 2) ? dPh : dPl;
                uint64_t db = (pass == 1) ? dVl : dVh;
#pragma unroll
                for (int ck = 0; ck < 4; ck++) {
                    bool en = !(t == 0 && pass == 0 && ck == 0);
                    mma_f16_ss(tmO, da + ck * 2, db + ck * 2, IDESC_O, en);
                }
            }
            TCGEN05_COMMIT(mbPV);
            if (t + 1 < NT) issue_S(t + 1);
        }
    }

    MBARRIER_WAIT_PARITY(mbPV, (NT - 1) & 1);
    TCGEN05_FENCE_AFTER();
    __syncthreads();

    // ---- epilogue: O/l -> split bf16 ----
    {
        const int ec0 = (wid >> 2) * 64;
        const float inv = 1.0f / l_sh[qrow];
        uint32_t o1[32], o2[32];
        TCGEN05_LD_32X32B_X32(o1, tmO + ec0);
        TCGEN05_WAIT_LD();
        TCGEN05_LD_32X32B_X32(o2, tmO + ec0 + 32);
        TCGEN05_WAIT_LD();
        TCGEN05_FENCE_BEFORE();
        size_t gb = (size_t)(b * SEQ + q0 + qrow) * DMODEL + h * DHD + ec0;
#pragma unroll
        for (int i = 0; i < 16; i++) {
            float v0 = __uint_as_float(o1[2 * i]) * inv;
            float v1 = __uint_as_float(o1[2 * i + 1]) * inv;
            uint32_t hp, lp;
            split2u32(v0, v1, hp, lp);
            *(uint32_t*)(g_Aoh + gb + 2 * i) = hp;
            *(uint32_t*)(g_Aol + gb + 2 * i) = lp;
        }
#pragma unroll
        for (int i = 0; i < 16; i++) {
            float v0 = __uint_as_float(o2[2 * i]) * inv;
            float v1 = __uint_as_float(o2[2 * i + 1]) * inv;
            uint32_t hp, lp;
            split2u32(v0, v1, hp, lp);
            *(uint32_t*)(g_Aoh + gb + 32 + 2 * i) = hp;
            *(uint32_t*)(g_Aol + gb + 32 + 2 * i) = lp;
        }
    }
    __syncthreads();
    if (wid == 0) {
        TCGEN05_RELINQUISH();
        TCGEN05_DEALLOC(tmem, 256);
    }
#else
    // ---------------- SIMT fallback (dead on GB300; correctness backstop) ---
    const int tid = threadIdx.x;
    if (tid >= ATQ) return;
    const int q = blockIdx.x * ATQ + tid;
    const int h = blockIdx.y;
    const int b = blockIdx.z;
    size_t qb = (size_t)(b * SEQ + q) * DMODEL + h * DHD;
    float l = 0.0f;
    float o[DHD];
    for (int d = 0; d < DHD; d++) o[d] = 0.0f;
    for (int k = 0; k < SEQ; k++) {
        size_t kb = (size_t)(b * SEQ + k) * DMODEL + h * DHD;
        float s = 0.0f;
        for (int d = 0; d < DHD; d++) {
            float qv = __bfloat162float(g_Qsh[qb + d]) + __bfloat162float(g_Qsl[qb + d]);
            float kv = __bfloat162float(g_Ksh[kb + d]) + __bfloat162float(g_Ksl[kb + d]);
            s += qv * kv;
        }
        float p = __expf(s);
        l += p;
        for (int d = 0; d < DHD; d++)
            o[d] += p * g_Vr[kb + d];
    }
    float inv = 1.0f / l;
    for (int d = 0; d < DHD; d++) {
        float v = o[d] * inv;
        __nv_bfloat16 hh = __float2bfloat16(v);
        g_Aoh[qb + d] = hh;
        g_Aol[qb + d] = __float2bfloat16(v - __bfloat162float(hh));
    }
#endif
}

// ===================== launcher =============================================
extern "C" void kernel_launch(void* const* d_in, const int* in_sizes, int n_in,
                              void* d_out, int out_size)
{
    const float* x  = (const float*)d_in[0];
    const float* Wq = (const float*)d_in[1];
    const float* Wk = (const float*)d_in[2];
    const float* Wv = (const float*)d_in[3];
    const float* Wo = (const float*)d_in[4];
    const float* bo = (const float*)d_in[5];
    float* out = (float*)d_out;

    float *Qr, *Kr, *Vr;
    bf16 *xh, *xl, *Wqh, *Wql, *Wkh, *Wkl, *Wvh, *Wvl, *Woh, *Wol, *Aoh, *Aol;
    cudaGetSymbolAddress((void**)&Qr, g_Qr);
    cudaGetSymbolAddress((void**)&Kr, g_Kr);
    cudaGetSymbolAddress((void**)&Vr, g_Vr);
    cudaGetSymbolAddress((void**)&xh, g_xh);
    cudaGetSymbolAddress((void**)&xl, g_xl);
    cudaGetSymbolAddress((void**)&Wqh, g_Wqh);
    cudaGetSymbolAddress((void**)&Wql, g_Wql);
    cudaGetSymbolAddress((void**)&Wkh, g_Wkh);
    cudaGetSymbolAddress((void**)&Wkl, g_Wkl);
    cudaGetSymbolAddress((void**)&Wvh, g_Wvh);
    cudaGetSymbolAddress((void**)&Wvl, g_Wvl);
    cudaGetSymbolAddress((void**)&Woh, g_Woh);
    cudaGetSymbolAddress((void**)&Wol, g_Wol);
    cudaGetSymbolAddress((void**)&Aoh, g_Aoh);
    cudaGetSymbolAddress((void**)&Aol, g_Aol);

    cudaFuncSetAttribute(gemm_kernel<false>,
                         cudaFuncAttributeMaxDynamicSharedMemorySize, GEMM_DSMEM);
    cudaFuncSetAttribute(gemm_kernel<true>,
                         cudaFuncAttributeMaxDynamicSharedMemorySize, GEMM_DSMEM);
    cudaFuncSetAttribute(attn_tc_kernel,
                         cudaFuncAttributeMaxDynamicSharedMemorySize, AT_DSMEM);
    cudaFuncSetAttribute(vtrans_kernel,
                         cudaFuncAttributeMaxDynamicSharedMemorySize, VT_SMEM);

    rope_table_kernel<<<(SEQ * (DHD / 2) + 255) / 256, 256>>>();

    const int NX = MROWS * DMODEL;
    const int NW = DMODEL * DMODEL;
    convert_split_kernel<<<NX / 4 / 256, 256>>>(x, xh, xl, NX);
    convert_split_kernel<<<NW / 4 / 256, 256>>>(Wq, Wqh, Wql, NW);
    convert_split_kernel<<<NW / 4 / 256, 256>>>(Wk, Wkh, Wkl, NW);
    convert_split_kernel<<<NW / 4 / 256, 256>>>(Wv, Wvh, Wvl, NW);
    convert_split_kernel<<<NW / 4 / 256, 256>>>(Wo, Woh, Wol, NW);

    dim3 gg(DMODEL / TCBN, MROWS / TCBM);
    gemm_kernel<false><<<gg, 256, GEMM_DSMEM>>>(xh, xl, Wqh, Wql, nullptr, Qr);
    gemm_kernel<false><<<gg, 256, GEMM_DSMEM>>>(xh, xl, Wkh, Wkl, nullptr, Kr);
    gemm_kernel<false><<<gg, 256, GEMM_DSMEM>>>(xh, xl, Wvh, Wvl, nullptr, Vr);

    rope_convert_kernel<<<MROWS, 1024>>>();
    vtrans_kernel<<<dim3(SEQ / 128, NH, BATCH), 256, VT_SMEM>>>();

    attn_tc_kernel<<<dim3(SEQ / ATQ, NH, BATCH), 256, AT_DSMEM>>>();

    gemm_kernel<true><<<gg, 256, GEMM_DSMEM>>>(Aoh, Aol, Woh, Wol, bo, out);
}

// round 13
// speedup vs baseline: 1.5262x; 1.5262x over previous
#include <cuda_runtime.h>
#include <cuda.h>
#include <cuda_bf16.h>
#include <cstdint>
#include <math.h>

// Problem dims (fixed)
#define BATCH  2
#define SEQ    2048
#define NH     16
#define DHD    128
#define DMODEL 2048
#define MROWS  (BATCH * SEQ)   // 4096
#define ATT_SCALE 0.08838834764831845f
#define NX (MROWS * DMODEL)
#define NW (DMODEL * DMODEL)

// ---- arch-feature gate: tcgen05 only exists in the sm_103a/'a'/'f' passes ----
#if defined(__CUDA_ARCH__)
#  if defined(__CUDA_ARCH_FEAT_SM103_ALL) || defined(__CUDA_ARCH_FEAT_SM100_ALL)
#    define HAS_TCGEN05 1
#  elif defined(__CUDA_ARCH_SPECIFIC__) && (__CUDA_ARCH_SPECIFIC__ >= 1000)
#    define HAS_TCGEN05 1
#  elif defined(__CUDA_ARCH_FAMILY_SPECIFIC__) && (__CUDA_ARCH_FAMILY_SPECIFIC__ >= 1000)
#    define HAS_TCGEN05 1
#  else
#    define HAS_TCGEN05 0
#  endif
#else
#  define HAS_TCGEN05 0
#endif

typedef __nv_bfloat16 bf16;

// ===================== generic helpers ======================================
__device__ __forceinline__ uint32_t smem_u32(const void* p) {
    uint32_t a;
    asm("{ .reg .u64 t; cvta.to.shared.u64 t, %1; cvt.u32.u64 %0, t; }"
        : "=r"(a) : "l"(p));
    return a;
}

__device__ __forceinline__ uint32_t elect_one_pred() {
    uint32_t pred;
    asm volatile(
        "{\n\t.reg .pred p;\n\telect.sync _|p, 0xFFFFFFFF;\n\tselp.b32 %0, 1, 0, p;\n\t}"
        : "=r"(pred));
    return pred;
}

#define MBARRIER_INIT(addr, count) \
    asm volatile("mbarrier.init.shared.b64 [%0], %1;" :: "r"((uint32_t)(addr)), "r"((uint32_t)(count)) : "memory")

#define MBARRIER_EXPECT_TX(addr, bytes) \
    asm volatile("mbarrier.arrive.expect_tx.shared.b64 _, [%0], %1;" \
        :: "r"((uint32_t)(addr)), "r"((uint32_t)(bytes)) : "memory")

#define MBARRIER_WAIT_PARITY(mbar_smem_addr, phase_parity) do { \
    uint32_t _mbar = (uint32_t)(mbar_smem_addr); \
    uint32_t _parity = (uint32_t)(phase_parity); \
    uint32_t _done; \
    asm volatile( \
        "{\n\t.reg .pred p;\n\t" \
        "mbarrier.try_wait.parity.acquire.cta.shared::cta.b64 p, [%1], %2;\n\t" \
        "selp.b32 %0, 1, 0, p;\n\t}" \
        : "=r"(_done) : "r"(_mbar), "r"(_parity) : "memory"); \
    if (!_done) { \
        asm volatile( \
            "{\n\t.reg .pred P1;\n\t" \
            "WAIT_LOOP_%=:\n\t" \
            "mbarrier.try_wait.parity.acquire.cta.shared::cta.b64 P1, [%0], %1, 0x989680;\n\t" \
            "@P1 bra.uni WAIT_DONE_%=;\n\t" \
            "bra.uni WAIT_LOOP_%=;\n\t" \
            "WAIT_DONE_%=:\n\t}" \
            :: "r"(_mbar), "r"(_parity) : "memory"); \
    } \
} while(0)

__device__ __forceinline__ uint32_t sw128(uint32_t o) { return o ^ ((o >> 3) & 0x70); }

__device__ __forceinline__ void split2u32(float a, float b, uint32_t& hp, uint32_t& lp) {
    __nv_bfloat16 ha = __float2bfloat16(a), hb = __float2bfloat16(b);
    float ra = a - __bfloat162float(ha);
    float rb = b - __bfloat162float(hb);
    __nv_bfloat16 la = __float2bfloat16(ra), lb = __float2bfloat16(rb);
    hp = ((uint32_t)__bfloat16_as_ushort(hb) << 16) | __bfloat16_as_ushort(ha);
    lp = ((uint32_t)__bfloat16_as_ushort(lb) << 16) | __bfloat16_as_ushort(la);
}

#if HAS_TCGEN05
// ===================== tcgen05 + TMA PTX (guarded) ==========================
#define TCGEN05_ALLOC(smem_result_addr, nCols) \
    asm volatile("tcgen05.alloc.cta_group::1.sync.aligned.shared::cta.b32 [%0], %1;" \
        :: "r"((uint32_t)(smem_result_addr)), "r"((uint32_t)(nCols)) : "memory")
#define TCGEN05_DEALLOC(tmem_addr, nCols) \
    asm volatile("tcgen05.dealloc.cta_group::1.sync.aligned.b32 %0, %1;" \
        :: "r"(tmem_addr), "r"((uint32_t)(nCols)))
#define TCGEN05_RELINQUISH() \
    asm volatile("tcgen05.relinquish_alloc_permit.cta_group::1.sync.aligned;")
#define TCGEN05_COMMIT(mbar_smem_addr) \
    asm volatile("tcgen05.commit.cta_group::1.mbarrier::arrive::one.shared::cluster.b64 [%0];" \
        :: "r"((uint32_t)(mbar_smem_addr)) : "memory")
#define TCGEN05_FENCE_AFTER() \
    asm volatile("tcgen05.fence::after_thread_sync;" ::: "memory")
#define TCGEN05_FENCE_BEFORE() \
    asm volatile("tcgen05.fence::before_thread_sync;" ::: "memory")
#define TCGEN05_WAIT_LD() \
    asm volatile("tcgen05.wait::ld.sync.aligned;" ::: "memory")
#define FENCE_PROXY_ASYNC_SHARED_CTA() \
    asm volatile("fence.proxy.async.shared::cta;" ::: "memory")

#define TMA_LOAD_2D(smem_addr, map_ptr, cx, cy, mbar) \
    asm volatile( \
        "cp.async.bulk.tensor.2d.shared::cta.global.tile.mbarrier::complete_tx::bytes " \
        "[%0], [%1, {%2, %3}], [%4];" \
        :: "r"((uint32_t)(smem_addr)), "l"(map_ptr), "r"((int)(cx)), "r"((int)(cy)), \
           "r"((uint32_t)(mbar)) : "memory")

#define TCGEN05_LD_32X32B_X32(r, tmem_addr) \
    asm volatile( \
        "tcgen05.ld.sync.aligned.32x32b.x32.b32 " \
        "{%0, %1, %2, %3, %4, %5, %6, %7, " \
        " %8, %9, %10, %11, %12, %13, %14, %15, " \
        " %16, %17, %18, %19, %20, %21, %22, %23, " \
        " %24, %25, %26, %27, %28, %29, %30, %31}, [%32];" \
        : "=r"((r)[0]),  "=r"((r)[1]),  "=r"((r)[2]),  "=r"((r)[3]), \
          "=r"((r)[4]),  "=r"((r)[5]),  "=r"((r)[6]),  "=r"((r)[7]), \
          "=r"((r)[8]),  "=r"((r)[9]),  "=r"((r)[10]), "=r"((r)[11]), \
          "=r"((r)[12]), "=r"((r)[13]), "=r"((r)[14]), "=r"((r)[15]), \
          "=r"((r)[16]), "=r"((r)[17]), "=r"((r)[18]), "=r"((r)[19]), \
          "=r"((r)[20]), "=r"((r)[21]), "=r"((r)[22]), "=r"((r)[23]), \
          "=r"((r)[24]), "=r"((r)[25]), "=r"((r)[26]), "=r"((r)[27]), \
          "=r"((r)[28]), "=r"((r)[29]), "=r"((r)[30]), "=r"((r)[31]) \
        : "r"(tmem_addr))

static constexpr uint64_t SMEM_DESC_BASE_SW128 =
    (uint64_t(2)  << 61) | (uint64_t(1) << 46) | (uint64_t(64) << 32) | (uint64_t(1) << 16);
#define MAKE_SMEM_DESC(base_addr) \
    (SMEM_DESC_BASE_SW128 | ((uint64_t)((base_addr) >> 4) & 0x3FFF))

__device__ __forceinline__ void mma_f16_ss(uint32_t d, uint64_t da, uint64_t db,
                                           uint32_t idesc, bool en) {
    uint32_t e = en ? 1u : 0u;
    asm volatile(
        "{\n\t.reg .pred p;\n\tsetp.ne.u32 p, %5, 0;\n\t"
        "tcgen05.mma.cta_group::1.kind::f16 [%0], %1, %2, %3, {%4, %4, %4, %4}, p;\n\t}"
        :: "r"(d), "l"(da), "l"(db), "r"(idesc), "r"(0u), "r"(e) : "memory");
}
#endif  // HAS_TCGEN05

// ===================== scratch ==============================================
__device__ float g_Qr[(size_t)MROWS * DMODEL];
__device__ float g_Kr[(size_t)MROWS * DMODEL];
__device__ float g_Vr[(size_t)MROWS * DMODEL];
__device__ float g_cos[SEQ * (DHD / 2)];
__device__ float g_sin[SEQ * (DHD / 2)];

__device__ bf16 g_xh[(size_t)NX];
__device__ bf16 g_xl[(size_t)NX];
__device__ bf16 g_Wqh[(size_t)NW];
__device__ bf16 g_Wql[(size_t)NW];
__device__ bf16 g_Wkh[(size_t)NW];
__device__ bf16 g_Wkl[(size_t)NW];
__device__ bf16 g_Wvh[(size_t)NW];
__device__ bf16 g_Wvl[(size_t)NW];
__device__ bf16 g_Woh[(size_t)NW];
__device__ bf16 g_Wol[(size_t)NW];
__device__ bf16 g_Qsh[(size_t)NX];
__device__ bf16 g_Qsl[(size_t)NX];
__device__ bf16 g_Ksh[(size_t)NX];
__device__ bf16 g_Ksl[(size_t)NX];
// V transposed per (b,h): [b][h][d=128][s=2048]
__device__ bf16 g_Vth[(size_t)NX];
__device__ bf16 g_Vtl[(size_t)NX];
__device__ bf16 g_Aoh[(size_t)NX];
__device__ bf16 g_Aol[(size_t)NX];

// ===== launch 1: fused converts (x, Wq, Wk, Wv, Wo) + RoPE table ============
__global__ void convert_all_kernel(const float* __restrict__ x,
                                   const float* __restrict__ Wq,
                                   const float* __restrict__ Wk,
                                   const float* __restrict__ Wv,
                                   const float* __restrict__ Wo)
{
    const int seg = blockIdx.y;
    if (seg == 5) {
        int idx = blockIdx.x * 256 + threadIdx.x;
        if (idx >= SEQ * (DHD / 2)) return;
        int s = idx / (DHD / 2);
        int i = idx % (DHD / 2);
        double inv = pow(10000.0, -(double)(2 * i) / (double)DHD);
        double f = (double)s * inv;
        g_cos[idx] = (float)cos(f);
        g_sin[idx] = (float)sin(f);
        return;
    }
    const float* in; bf16* hi; bf16* lo; int n;
    switch (seg) {
        case 0: in = x;  hi = g_xh;  lo = g_xl;  n = NX; break;
        case 1: in = Wq; hi = g_Wqh; lo = g_Wql; n = NW; break;
        case 2: in = Wk; hi = g_Wkh; lo = g_Wkl; n = NW; break;
        case 3: in = Wv; hi = g_Wvh; lo = g_Wvl; n = NW; break;
        default: in = Wo; hi = g_Woh; lo = g_Wol; n = NW; break;
    }
    int i = (blockIdx.x * 256 + threadIdx.x) * 4;
    if (i >= n) return;
    float4 v = *(const float4*)(in + i);
    uint32_t h0, l0, h1, l1;
    split2u32(v.x, v.y, h0, l0);
    split2u32(v.z, v.w, h1, l1);
    *(uint2*)(hi + i) = make_uint2(h0, h1);
    *(uint2*)(lo + i) = make_uint2(l0, l1);
}

__device__ __forceinline__ void split_store(bf16* hi, bf16* lo, size_t idx, float v) {
    __nv_bfloat16 h = __float2bfloat16(v);
    float r = v - __bfloat162float(h);
    hi[idx] = h;
    lo[idx] = __float2bfloat16(r);
}

// ===== launch 5: fused RoPE(Q,K)+split AND V transpose+split ================
#define RV_SMEM (128 * 130 * 4)
__global__ void rope_vtrans_kernel() {
    extern __shared__ float vs[];
    const int bx = blockIdx.x;
    const int tid = threadIdx.x;
    if (bx < MROWS) {
        // RoPE path: 1024 threads, one (b,s) row
        const int s = bx % SEQ;
        const int h = tid >> 6;
        const int i = tid & 63;
        size_t base = (size_t)bx * DMODEL + (size_t)h * DHD;
        float c  = g_cos[s * 64 + i];
        float sn = g_sin[s * 64 + i];

        float q1 = g_Qr[base + i];
        float q2 = g_Qr[base + i + 64];
        split_store(g_Qsh, g_Qsl, base + i,      (q1 * c - q2 * sn) * ATT_SCALE);
        split_store(g_Qsh, g_Qsl, base + i + 64, (q2 * c + q1 * sn) * ATT_SCALE);

        float k1 = g_Kr[base + i];
        float k2 = g_Kr[base + i + 64];
        split_store(g_Ksh, g_Ksl, base + i,      k1 * c - k2 * sn);
        split_store(g_Ksh, g_Ksl, base + i + 64, k2 * c + k1 * sn);
    } else {
        // V transpose path
        const int v = bx - MROWS;
        const int s0 = (v & 15) * 128;
        const int h  = (v >> 4) & 15;
        const int b  = v >> 8;
#pragma unroll
        for (int it = 0; it < 4; it++) {
            int f4 = tid + it * 1024;
            int s = f4 >> 5;
            int c4 = (f4 & 31) * 4;
            float4 vv = *(const float4*)(g_Vr + (size_t)(b * SEQ + s0 + s) * DMODEL
                                              + h * DHD + c4);
            vs[s * 130 + c4 + 0] = vv.x;
            vs[s * 130 + c4 + 1] = vv.y;
            vs[s * 130 + c4 + 2] = vv.z;
            vs[s * 130 + c4 + 3] = vv.w;
        }
        __syncthreads();
        const int d = tid >> 3;
        const int p = tid & 7;
        size_t gb = ((size_t)(b * NH + h) * DHD + d) * SEQ + s0 + p * 16;
#pragma unroll
        for (int gg = 0; gg < 2; gg++) {
            uint32_t hh[4], ll[4];
#pragma unroll
            for (int q = 0; q < 4; q++) {
                int s = p * 16 + gg * 8 + 2 * q;
                split2u32(vs[s * 130 + d], vs[(s + 1) * 130 + d], hh[q], ll[q]);
            }
            *(uint4*)(g_Vth + gb + gg * 8) = make_uint4(hh[0], hh[1], hh[2], hh[3]);
            *(uint4*)(g_Vtl + gb + gg * 8) = make_uint4(ll[0], ll[1], ll[2], ll[3]);
        }
    }
}

// ===================== TMA GEMM 128x256 tiles (bf16 split) ==================
#define TCBM 128
#define TCBN 256
#define TCBK 64
#define NCHUNK (DMODEL / TCBK)        // 32
#define STAGE_BYTES 98304             // Ah 16K + Al 16K + Bh 32K + Bl 32K
#define GEMM_DSMEM (2 * STAGE_BYTES + 1024)

#define GEMM_IDESC ((1u<<4) | (1u<<7) | (1u<<10) | (32u<<17) | (8u<<24))  // N=256,M=128

template <bool BIAS>
__global__ void __launch_bounds__(256) gemm_kernel(
    const __grid_constant__ CUtensorMap mAh, const __grid_constant__ CUtensorMap mAl,
    const __grid_constant__ CUtensorMap mBh, const __grid_constant__ CUtensorMap mBl,
    const bf16* __restrict__ Ahi, const bf16* __restrict__ Alo,
    const bf16* __restrict__ Whi, const bf16* __restrict__ Wlo,
    const float* __restrict__ bias, float* __restrict__ C)
{
#if HAS_TCGEN05
    extern __shared__ char dsm[];
    __shared__ uint32_t s_tmem[1];
    __shared__ __align__(8) uint64_t s_mbar[4];   // full0, full1, done0, done1

    uint32_t dyn = smem_u32(dsm);
    uint32_t base = (dyn + 1023) & ~1023u;
    char* bufc = dsm + (base - dyn);

    const int tid = threadIdx.x;
    const int wid = tid >> 5, lid = tid & 31;
    const int m0 = blockIdx.y * TCBM;
    const int n0 = blockIdx.x * TCBN;

    if (wid == 0) TCGEN05_ALLOC(smem_u32(s_tmem), 256);
    if (tid == 0) {
        MBARRIER_INIT(smem_u32(&s_mbar[0]), 1);
        MBARRIER_INIT(smem_u32(&s_mbar[1]), 1);
        MBARRIER_INIT(smem_u32(&s_mbar[2]), 1);
        MBARRIER_INIT(smem_u32(&s_mbar[3]), 1);
    }
    __syncthreads();
    const uint32_t tmem = s_tmem[0];
    const uint32_t full[2] = { smem_u32(&s_mbar[0]), smem_u32(&s_mbar[1]) };
    const uint32_t done[2] = { smem_u32(&s_mbar[2]), smem_u32(&s_mbar[3]) };

    if (wid == 0 && elect_one_pred()) {
        auto tma4 = [&](int st, int k0) {
            uint32_t sb = smem_u32(bufc) + st * STAGE_BYTES;
            MBARRIER_EXPECT_TX(full[st], STAGE_BYTES);
            TMA_LOAD_2D(sb,         &mAh, k0, m0, full[st]);
            TMA_LOAD_2D(sb + 16384, &mAl, k0, m0, full[st]);
            TMA_LOAD_2D(sb + 32768, &mBh, k0, n0, full[st]);
            TMA_LOAD_2D(sb + 65536, &mBl, k0, n0, full[st]);
        };
        tma4(0, 0);
        tma4(1, TCBK);
        for (int c = 0; c < NCHUNK; c++) {
            const int st = c & 1;
            const uint32_t ph = (c >> 1) & 1;
            MBARRIER_WAIT_PARITY(full[st], ph);
            uint32_t sb = smem_u32(bufc) + st * STAGE_BYTES;
            uint64_t dAh = MAKE_SMEM_DESC(sb);
            uint64_t dAl = MAKE_SMEM_DESC(sb + 16384);
            uint64_t dBh = MAKE_SMEM_DESC(sb + 32768);
            uint64_t dBl = MAKE_SMEM_DESC(sb + 65536);
            uint64_t pa[3] = {dAh, dAh, dAl};
            uint64_t pb[3] = {dBh, dBl, dBh};
#pragma unroll
            for (int pass = 0; pass < 3; pass++) {
#pragma unroll
                for (int k = 0; k < 4; k++) {
                    bool en = !(c == 0 && pass == 0 && k == 0);
                    mma_f16_ss(tmem, pa[pass] + k * 2, pb[pass] + k * 2, GEMM_IDESC, en);
                }
            }
            TCGEN05_COMMIT(done[st]);
            if (c + 2 < NCHUNK) {
                MBARRIER_WAIT_PARITY(done[st], ph);   // stage free after MMA(c)
                tma4(st, (c + 2) * TCBK);
            }
        }
        MBARRIER_WAIT_PARITY(done[0], 1);   // last commit on stage 0: c=30, phase 1
        MBARRIER_WAIT_PARITY(done[1], 1);   // last commit on stage 1: c=31, phase 1
    }
    __syncthreads();
    TCGEN05_FENCE_AFTER();

    if (wid < 4) {
        const int mrow = m0 + wid * 32 + lid;
#pragma unroll
        for (int part = 0; part < 8; part++) {
            uint32_t d[32];
            TCGEN05_LD_32X32B_X32(d, tmem + part * 32);
            TCGEN05_WAIT_LD();
            float* crow = C + (size_t)mrow * DMODEL + n0 + part * 32;
#pragma unroll
            for (int q = 0; q < 8; q++) {
                float4 v;
                v.x = __uint_as_float(d[4*q + 0]);
                v.y = __uint_as_float(d[4*q + 1]);
                v.z = __uint_as_float(d[4*q + 2]);
                v.w = __uint_as_float(d[4*q + 3]);
                if (BIAS) {
                    const float* bp = bias + n0 + part * 32 + 4 * q;
                    v.x += bp[0]; v.y += bp[1]; v.z += bp[2]; v.w += bp[3];
                }
                *(float4*)(crow + 4 * q) = v;
            }
        }
        TCGEN05_FENCE_BEFORE();
    }
    __syncthreads();
    if (wid == 0) {
        TCGEN05_RELINQUISH();
        TCGEN05_DEALLOC(tmem, 256);
    }
#else
    // ---------------- SIMT fallback (dead on GB300; correctness backstop) ---
    const int tid = threadIdx.x;
    const int m0 = blockIdx.y * TCBM;
    const int n0 = blockIdx.x * TCBN;
    const int tx = tid % 16;
    const int ty = tid / 16;
    for (int jj = 0; jj < 2; jj++) {
        float acc[8][8];
        for (int i = 0; i < 8; i++)
            for (int j = 0; j < 8; j++) acc[i][j] = 0.0f;
        for (int k = 0; k < DMODEL; k++) {
            float a[8], bb[8];
            for (int i = 0; i < 8; i++) {
                size_t ai = (size_t)(m0 + ty * 8 + i) * DMODEL + k;
                a[i] = __bfloat162float(Ahi[ai]) + __bfloat162float(Alo[ai]);
            }
            for (int j = 0; j < 8; j++) {
                size_t bi = (size_t)(n0 + jj * 128 + tx * 8 + j) * DMODEL + k;
                bb[j] = __bfloat162float(Whi[bi]) + __bfloat162float(Wlo[bi]);
            }
            for (int i = 0; i < 8; i++)
                for (int j = 0; j < 8; j++) acc[i][j] += a[i] * bb[j];
        }
        for (int i = 0; i < 8; i++)
            for (int j = 0; j < 8; j++) {
                float v = acc[i][j];
                if (BIAS) v += bias[n0 + jj * 128 + tx * 8 + j];
                C[(size_t)(m0 + ty * 8 + i) * DMODEL + n0 + jj * 128 + tx * 8 + j] = v;
            }
    }
#endif
}

// ===================== tcgen05 flash attention (pipelined, R8) ==============
#define ATQ 128
#define ATK 64
#define NT (SEQ / ATK)           // 32
#define AT_DSMEM (229376 + 1024)

#define IDESC_S ((1u<<4) | (1u<<7) | (1u<<10) | (8u<<17)  | (8u<<24))   // N=64
#define IDESC_O ((1u<<4) | (1u<<7) | (1u<<10) | (16u<<17) | (8u<<24))   // N=128

__global__ void __launch_bounds__(256, 1) attn_tc_kernel() {
#if HAS_TCGEN05
    extern __shared__ char smem_dyn[];
    __shared__ uint32_t s_tmem[1];
    __shared__ __align__(8) uint64_t s_mbar[3];
    __shared__ float l_sh[ATQ];

    uint32_t dyn = smem_u32(smem_dyn);
    uint32_t ab = (dyn + 1023) & ~1023u;
    char* B = smem_dyn + (ab - dyn);
    char* Q0h = B;
    char* Q1h = B + 16384;
    char* Q0l = B + 32768;
    char* Q1l = B + 49152;
    char* Kst[2];  Kst[0] = B + 65536;  Kst[1] = B + 98304;
    char* Vst[2];  Vst[0] = B + 131072; Vst[1] = B + 163840;
    char* Phi = B + 196608;
    char* Plo = B + 212992;

    const int tid = threadIdx.x;
    const int wid = tid >> 5, lid = tid & 31;
    const int q0 = blockIdx.x * ATQ;
    const int h  = blockIdx.y;
    const int b  = blockIdx.z;

    if (wid == 0) TCGEN05_ALLOC(smem_u32(s_tmem), 256);
    if (tid == 0) {
        MBARRIER_INIT(smem_u32(&s_mbar[0]), 1);
        MBARRIER_INIT(smem_u32(&s_mbar[1]), 1);
        MBARRIER_INIT(smem_u32(&s_mbar[2]), 1);
    }
    for (int i = tid; i < ATQ; i += 256) l_sh[i] = 0.0f;
    __syncthreads();
    const uint32_t tmem = s_tmem[0];
    const uint32_t tmO = tmem + 128;
    const uint32_t mbS[2] = { smem_u32(&s_mbar[0]), smem_u32(&s_mbar[1]) };
    const uint32_t mbPV = smem_u32(&s_mbar[2]);

    // ---- persistent Q tile ----
    {
        const int r = tid >> 1, half = tid & 1;
        const bf16* gh = g_Qsh + (size_t)(b * SEQ + q0 + r) * DMODEL + h * DHD + half * 64;
        const bf16* gl = g_Qsl + (size_t)(b * SEQ + q0 + r) * DMODEL + h * DHD + half * 64;
        char* dh = half ? Q1h : Q0h;
        char* dl = half ? Q1l : Q0l;
#pragma unroll
        for (int j = 0; j < 8; j++) {
            uint32_t off = sw128((uint32_t)(r * 128 + j * 16));
            *(uint4*)(dh + off) = *(const uint4*)(gh + j * 8);
            *(uint4*)(dl + off) = *(const uint4*)(gl + j * 8);
        }
    }

    const uint64_t dQ[2][2] = {
        { MAKE_SMEM_DESC(smem_u32(Q0h)), MAKE_SMEM_DESC(smem_u32(Q1h)) },
        { MAKE_SMEM_DESC(smem_u32(Q0l)), MAKE_SMEM_DESC(smem_u32(Q1l)) } };
    const uint64_t dPh = MAKE_SMEM_DESC(smem_u32(Phi));
    const uint64_t dPl = MAKE_SMEM_DESC(smem_u32(Plo));

    auto load_k = [&](int st, int tt) {
        const int k0 = tt * ATK;
        const int r = tid >> 2, seg = tid & 3;
        const int d0 = seg * 32;
        char* dh = Kst[st] + (seg >> 1) * 8192;
        char* dl = dh + 16384;
        const bf16* gh = g_Ksh + (size_t)(b * SEQ + k0 + r) * DMODEL + h * DHD + d0;
        const bf16* gl = g_Ksl + (size_t)(b * SEQ + k0 + r) * DMODEL + h * DHD + d0;
#pragma unroll
        for (int j = 0; j < 4; j++) {
            uint32_t off = sw128((uint32_t)(r * 128 + (d0 & 63) * 2 + j * 16));
            *(uint4*)(dh + off) = *(const uint4*)(gh + j * 8);
            *(uint4*)(dl + off) = *(const uint4*)(gl + j * 8);
        }
    };
    auto load_v = [&](int st, int tt) {
        const int k0 = tt * ATK;
        const int d = tid >> 1, half = tid & 1;
        size_t gb = ((size_t)(b * NH + h) * DHD + d) * SEQ + k0 + half * 32;
        char* vh = Vst[st];
        char* vl = Vst[st] + 16384;
#pragma unroll
        for (int j = 0; j < 4; j++) {
            uint32_t off = sw128((uint32_t)(d * 128 + half * 64 + j * 16));
            *(uint4*)(vh + off) = *(const uint4*)(g_Vth + gb + j * 8);
            *(uint4*)(vl + off) = *(const uint4*)(g_Vtl + gb + j * 8);
        }
    };

    auto issue_S = [&](int tt) {
        const uint32_t dst = tmem + (tt & 1) * 64;
        uint64_t dKh = MAKE_SMEM_DESC(smem_u32(Kst[tt & 1]));
        uint64_t dK1h = MAKE_SMEM_DESC(smem_u32(Kst[tt & 1] + 8192));
        uint64_t dKl = MAKE_SMEM_DESC(smem_u32(Kst[tt & 1] + 16384));
        uint64_t dK1l = MAKE_SMEM_DESC(smem_u32(Kst[tt & 1] + 24576));
        uint64_t kk[2][2] = { {dKh, dK1h}, {dKl, dK1l} };
        const int pa[3] = {0, 0, 1};
        const int pb[3] = {0, 1, 0};
#pragma unroll
        for (int pass = 0; pass < 3; pass++) {
#pragma unroll
            for (int cd = 0; cd < 8; cd++) {
                uint64_t da = dQ[pa[pass]][cd >> 2] + (cd & 3) * 2;
                uint64_t db = kk[pb[pass]][cd >> 2] + (cd & 3) * 2;
                mma_f16_ss(dst, da, db, IDESC_S, !(pass == 0 && cd == 0));
            }
        }
        TCGEN05_COMMIT(mbS[tt & 1]);
    };

    load_k(0, 0);
    load_v(0, 0);
    FENCE_PROXY_ASYNC_SHARED_CTA();
    __syncthreads();
    if (wid == 0 && elect_one_pred()) issue_S(0);

    const int qrow = (wid & 3) * 32 + lid;
    const int c0 = (wid >> 2) * 32;

    for (int t = 0; t < NT; t++) {
        if (t >= 1) MBARRIER_WAIT_PARITY(mbPV, (t - 1) & 1);
        if (t + 1 < NT) {
            load_k((t + 1) & 1, t + 1);
            load_v((t + 1) & 1, t + 1);
        }
        MBARRIER_WAIT_PARITY(mbS[t & 1], (t >> 1) & 1);
        TCGEN05_FENCE_AFTER();
        {
            uint32_t sr[32];
            TCGEN05_LD_32X32B_X32(sr, tmem + (t & 1) * 64 + c0);
            TCGEN05_WAIT_LD();
            TCGEN05_FENCE_BEFORE();
            float rs = 0.0f;
            uint32_t hp[16], lp[16];
#pragma unroll
            for (int i = 0; i < 16; i++) {
                float p0 = __expf(__uint_as_float(sr[2 * i]));
                float p1 = __expf(__uint_as_float(sr[2 * i + 1]));
                rs += p0 + p1;
                split2u32(p0, p1, hp[i], lp[i]);
            }
#pragma unroll
            for (int i = 0; i < 16; i++) {
                uint32_t off = sw128((uint32_t)(qrow * 128 + (c0 + 2 * i) * 2));
                *(uint32_t*)(Phi + off) = hp[i];
                *(uint32_t*)(Plo + off) = lp[i];
            }
            atomicAdd(&l_sh[qrow], rs);
        }
        FENCE_PROXY_ASYNC_SHARED_CTA();
        __syncthreads();
        if (wid == 0 && elect_one_pred()) {
            uint64_t dVh = MAKE_SMEM_DESC(smem_u32(Vst[t & 1]));
            uint64_t dVl = MAKE_SMEM_DESC(smem_u32(Vst[t & 1] + 16384));
#pragma unroll
            for (int pass = 0; pass < 3; pass++) {
                uint64_t da = (pass < 2) ? dPh : dPl;
                uint64_t db = (pass == 1) ? dVl : dVh;
#pragma unroll
                for (int ck = 0; ck < 4; ck++) {
                    bool en = !(t == 0 && pass == 0 && ck == 0);
                    mma_f16_ss(tmO, da + ck * 2, db + ck * 2, IDESC_O, en);
                }
            }
            TCGEN05_COMMIT(mbPV);
            if (t + 1 < NT) issue_S(t + 1);
        }
    }

    MBARRIER_WAIT_PARITY(mbPV, (NT - 1) & 1);
    TCGEN05_FENCE_AFTER();
    __syncthreads();

    {
        const int ec0 = (wid >> 2) * 64;
        const float inv = 1.0f / l_sh[qrow];
        uint32_t o1[32], o2[32];
        TCGEN05_LD_32X32B_X32(o1, tmO + ec0);
        TCGEN05_WAIT_LD();
        TCGEN05_LD_32X32B_X32(o2, tmO + ec0 + 32);
        TCGEN05_WAIT_LD();
        TCGEN05_FENCE_BEFORE();
        size_t gb = (size_t)(b * SEQ + q0 + qrow) * DMODEL + h * DHD + ec0;
#pragma unroll
        for (int i = 0; i < 16; i++) {
            float v0 = __uint_as_float(o1[2 * i]) * inv;
            float v1 = __uint_as_float(o1[2 * i + 1]) * inv;
            uint32_t hp, lp;
            split2u32(v0, v1, hp, lp);
            *(uint32_t*)(g_Aoh + gb + 2 * i) = hp;
            *(uint32_t*)(g_Aol + gb + 2 * i) = lp;
        }
#pragma unroll
        for (int i = 0; i < 16; i++) {
            float v0 = __uint_as_float(o2[2 * i]) * inv;
            float v1 = __uint_as_float(o2[2 * i + 1]) * inv;
            uint32_t hp, lp;
            split2u32(v0, v1, hp, lp);
            *(uint32_t*)(g_Aoh + gb + 32 + 2 * i) = hp;
            *(uint32_t*)(g_Aol + gb + 32 + 2 * i) = lp;
        }
    }
    __syncthreads();
    if (wid == 0) {
        TCGEN05_RELINQUISH();
        TCGEN05_DEALLOC(tmem, 256);
    }
#else
    // ---------------- SIMT fallback (dead on GB300; correctness backstop) ---
    const int tid = threadIdx.x;
    if (tid >= ATQ) return;
    const int q = blockIdx.x * ATQ + tid;
    const int h = blockIdx.y;
    const int b = blockIdx.z;
    size_t qb = (size_t)(b * SEQ + q) * DMODEL + h * DHD;
    float l = 0.0f;
    float o[DHD];
    for (int d = 0; d < DHD; d++) o[d] = 0.0f;
    for (int k = 0; k < SEQ; k++) {
        size_t kb = (size_t)(b * SEQ + k) * DMODEL + h * DHD;
        float s = 0.0f;
        for (int d = 0; d < DHD; d++) {
            float qv = __bfloat162float(g_Qsh[qb + d]) + __bfloat162float(g_Qsl[qb + d]);
            float kv = __bfloat162float(g_Ksh[kb + d]) + __bfloat162float(g_Ksl[kb + d]);
            s += qv * kv;
        }
        float p = __expf(s);
        l += p;
        for (int d = 0; d < DHD; d++)
            o[d] += p * g_Vr[kb + d];
    }
    float inv = 1.0f / l;
    for (int d = 0; d < DHD; d++) {
        float v = o[d] * inv;
        __nv_bfloat16 hh = __float2bfloat16(v);
        g_Aoh[qb + d] = hh;
        g_Aol[qb + d] = __float2bfloat16(v - __bfloat162float(hh));
    }
#endif
}

// ===================== launcher =============================================
typedef CUresult (*EncodeTiledFn)(
    CUtensorMap*, CUtensorMapDataType, cuuint32_t, void*,
    const cuuint64_t*, const cuuint64_t*, const cuuint32_t*, const cuuint32_t*,
    CUtensorMapInterleave, CUtensorMapSwizzle, CUtensorMapL2promotion,
    CUtensorMapFloatOOBfill);

static void encode_map(EncodeTiledFn fn, CUtensorMap* m, void* p,
                       int nrows, int box_rows)
{
    cuuint64_t dims[2]    = { (cuuint64_t)DMODEL, (cuuint64_t)nrows };
    cuuint64_t strides[1] = { (cuuint64_t)DMODEL * 2 };
    cuuint32_t box[2]     = { 64u, (cuuint32_t)box_rows };
    cuuint32_t es[2]      = { 1u, 1u };
    fn(m, CU_TENSOR_MAP_DATA_TYPE_BFLOAT16, 2, p, dims, strides, box, es,
       CU_TENSOR_MAP_INTERLEAVE_NONE, CU_TENSOR_MAP_SWIZZLE_128B,
       CU_TENSOR_MAP_L2_PROMOTION_L2_128B, CU_TENSOR_MAP_FLOAT_OOB_FILL_NONE);
}

extern "C" void kernel_launch(void* const* d_in, const int* in_sizes, int n_in,
                              void* d_out, int out_size)
{
    const float* x  = (const float*)d_in[0];
    const float* Wq = (const float*)d_in[1];
    const float* Wk = (const float*)d_in[2];
    const float* Wv = (const float*)d_in[3];
    const float* Wo = (const float*)d_in[4];
    const float* bo = (const float*)d_in[5];
    float* out = (float*)d_out;

    float *Qr, *Kr, *Vr;
    bf16 *xh, *xl, *Wqh, *Wql, *Wkh, *Wkl, *Wvh, *Wvl, *Woh, *Wol, *Aoh, *Aol;
    cudaGetSymbolAddress((void**)&Qr, g_Qr);
    cudaGetSymbolAddress((void**)&Kr, g_Kr);
    cudaGetSymbolAddress((void**)&Vr, g_Vr);
    cudaGetSymbolAddress((void**)&xh, g_xh);
    cudaGetSymbolAddress((void**)&xl, g_xl);
    cudaGetSymbolAddress((void**)&Wqh, g_Wqh);
    cudaGetSymbolAddress((void**)&Wql, g_Wql);
    cudaGetSymbolAddress((void**)&Wkh, g_Wkh);
    cudaGetSymbolAddress((void**)&Wkl, g_Wkl);
    cudaGetSymbolAddress((void**)&Wvh, g_Wvh);
    cudaGetSymbolAddress((void**)&Wvl, g_Wvl);
    cudaGetSymbolAddress((void**)&Woh, g_Woh);
    cudaGetSymbolAddress((void**)&Wol, g_Wol);
    cudaGetSymbolAddress((void**)&Aoh, g_Aoh);
    cudaGetSymbolAddress((void**)&Aol, g_Aol);

    // driver entry point for tensor-map encoding (no -lcuda needed)
    EncodeTiledFn encfn = nullptr;
    cudaDriverEntryPointQueryResult qr;
    cudaGetDriverEntryPoint("cuTensorMapEncodeTiled", (void**)&encfn,
                            cudaEnableDefault, &qr);

    // tensor maps: A-side box 64x128, B-side box 64x256
    CUtensorMap mxh, mxl, mqh, mql, mkh, mkl, mvh, mvl, moh, mol, mah, mal;
    encode_map(encfn, &mxh, xh, MROWS, 128);
    encode_map(encfn, &mxl, xl, MROWS, 128);
    encode_map(encfn, &mah, Aoh, MROWS, 128);
    encode_map(encfn, &mal, Aol, MROWS, 128);
    encode_map(encfn, &mqh, Wqh, DMODEL, 256);
    encode_map(encfn, &mql, Wql, DMODEL, 256);
    encode_map(encfn, &mkh, Wkh, DMODEL, 256);
    encode_map(encfn, &mkl, Wkl, DMODEL, 256);
    encode_map(encfn, &mvh, Wvh, DMODEL, 256);
    encode_map(encfn, &mvl, Wvl, DMODEL, 256);
    encode_map(encfn, &moh, Woh, DMODEL, 256);
    encode_map(encfn, &mol, Wol, DMODEL, 256);

    cudaFuncSetAttribute(gemm_kernel<false>,
                         cudaFuncAttributeMaxDynamicSharedMemorySize, GEMM_DSMEM);
    cudaFuncSetAttribute(gemm_kernel<true>,
                         cudaFuncAttributeMaxDynamicSharedMemorySize, GEMM_DSMEM);
    cudaFuncSetAttribute(attn_tc_kernel,
                         cudaFuncAttributeMaxDynamicSharedMemorySize, AT_DSMEM);
    cudaFuncSetAttribute(rope_vtrans_kernel,
                         cudaFuncAttributeMaxDynamicSharedMemorySize, RV_SMEM);

    // Launch order chosen so ncu (-s 5 -c 1) captures launch #6 = attention.
    // 1: fused converts + rope table
    convert_all_kernel<<<dim3(NX / 4 / 256, 6), 256>>>(x, Wq, Wk, Wv, Wo);

    // 2-4: QKV projections (TMA GEMM)
    dim3 gg(DMODEL / TCBN, MROWS / TCBM);
    gemm_kernel<false><<<gg, 256, GEMM_DSMEM>>>(mxh, mxl, mqh, mql,
                                                xh, xl, Wqh, Wql, nullptr, Qr);
    gemm_kernel<false><<<gg, 256, GEMM_DSMEM>>>(mxh, mxl, mkh, mkl,
                                                xh, xl, Wkh, Wkl, nullptr, Kr);
    gemm_kernel<false><<<gg, 256, GEMM_DSMEM>>>(mxh, mxl, mvh, mvl,
                                                xh, xl, Wvh, Wvl, nullptr, Vr);

    // 5: fused RoPE(Q,K) + V transpose
    rope_vtrans_kernel<<<MROWS + (SEQ / 128) * NH * BATCH, 1024, RV_SMEM>>>();

    // 6: attention (profiled)
    attn_tc_kernel<<<dim3(SEQ / ATQ, NH, BATCH), 256, AT_DSMEM>>>();

    // 7: output projection + bias
    gemm_kernel<true><<<gg, 256, GEMM_DSMEM>>>(mah, mal, moh, mol,
                                               Aoh, Aol, Woh, Wol, bo, out);
}